// round 9
// baseline (speedup 1.0000x reference)
#include <cuda_runtime.h>
#include <cuda_bf16.h>
#include <cstdint>

#define VOCAB 20000
#define D     512
#define B     64
#define S     256
#define C     16
#define G4D   (4*D)      // 2048

// ---------------- scratch (device globals; no allocation allowed) ----------
__device__ float g_x[S*B*D];        // [s][b][d]
__device__ float g_gx[S*B*G4D];     // [s][b][4D]
__device__ float g_h[B*D];
__device__ float g_final[B*D];
__device__ volatile unsigned g_flags[128];
__device__ volatile unsigned g_release;

// ---------------- helpers ---------------------------------------------------
__device__ __forceinline__ float cvt_tf32(float x) {
    uint32_t u;
    asm("cvt.rna.tf32.f32 %0, %1;" : "=r"(u) : "f"(x));
    return __uint_as_float(u);
}

__device__ __forceinline__ void mma_tf32(float* c, const uint32_t* a, const uint32_t* b) {
    asm volatile(
        "mma.sync.aligned.m16n8k8.row.col.f32.tf32.tf32.f32 "
        "{%0,%1,%2,%3}, {%4,%5,%6,%7}, {%8,%9}, {%0,%1,%2,%3};"
        : "+f"(c[0]), "+f"(c[1]), "+f"(c[2]), "+f"(c[3])
        : "r"(a[0]), "r"(a[1]), "r"(a[2]), "r"(a[3]),
          "r"(b[0]), "r"(b[1]));
}

// packed fp32x2 FMA (Blackwell): acc.lo += a.lo*b.lo ; acc.hi += a.hi*b.hi
__device__ __forceinline__ void fma2(unsigned long long& acc,
                                     unsigned long long a, unsigned long long b) {
    asm("fma.rn.f32x2 %0, %1, %2, %0;" : "+l"(acc) : "l"(a), "l"(b));
}

__device__ __forceinline__ float red2(unsigned long long a) {
    return __uint_as_float((unsigned)a) + __uint_as_float((unsigned)(a >> 32));
}

template<int N> __device__ __forceinline__ void cpwait() {
    asm volatile("cp.async.wait_group %0;" :: "n"(N) : "memory");
}
__device__ __forceinline__ void cpasync16(uint32_t dst, const void* src) {
    asm volatile("cp.async.cg.shared.global [%0], [%1], 16;" :: "r"(dst), "l"(src) : "memory");
}
__device__ __forceinline__ void cpcommit() {
    asm volatile("cp.async.commit_group;" ::: "memory");
}

// exact-ish fast activations (rel err ~2^-22; NOT the 2^-11 approx instrs)
__device__ __forceinline__ float fast_sigmoid(float x) {
    return __fdividef(1.f, 1.f + __expf(-x));
}
__device__ __forceinline__ float fast_tanh(float x) {
    float e = __expf(-2.f * fabsf(x));          // in (0,1], no overflow
    float t = __fdividef(1.f - e, 1.f + e);
    return copysignf(t, x);
}

// ---------------- K1: embedding gather + sum over codes ---------------------
__global__ void k1_embed(const int* __restrict__ seqs, const float* __restrict__ emb) {
    __shared__ int sidx[C];
    int bs  = blockIdx.x;
    int tid = threadIdx.x;
    if (tid < C) sidx[tid] = seqs[bs * C + tid];
    __syncthreads();
    int b = bs >> 8, s = bs & 255;
    float4 acc = make_float4(0.f, 0.f, 0.f, 0.f);
#pragma unroll
    for (int c = 0; c < C; c++) {
        int idx = sidx[c];
        if (idx != VOCAB) {
            float4 v = __ldg(((const float4*)(emb + (size_t)idx * D)) + tid);
            acc.x += v.x; acc.y += v.y; acc.z += v.z; acc.w += v.w;
        }
    }
    *(((float4*)(g_x + (size_t)(s * B + b) * D)) + tid) = acc;
}

// ---------------- K2: gates_x = x @ w_ih^T  (tf32 mma) -----------------------
__global__ void __launch_bounds__(256) k2_gemm(const float* __restrict__ Bw) {
    __shared__ float As[128][36];
    __shared__ float Bs[128][36];

    int tid  = threadIdx.x;
    int warp = tid >> 5, lane = tid & 31;
    int g    = lane >> 2, tig = lane & 3;
    int wm   = (warp & 1) * 64;
    int wn   = (warp >> 1) * 32;
    int bm0  = blockIdx.y * 128;
    int bn0  = blockIdx.x * 128;

    float acc[4][4][4];
#pragma unroll
    for (int mt = 0; mt < 4; mt++)
#pragma unroll
        for (int nt = 0; nt < 4; nt++)
#pragma unroll
            for (int r = 0; r < 4; r++) acc[mt][nt][r] = 0.f;

    for (int kt = 0; kt < D; kt += 32) {
#pragma unroll
        for (int i = 0; i < 4; i++) {
            int f   = tid + i * 256;
            int row = f >> 3, cc = f & 7;
            float4 v = *(const float4*)(g_x + (size_t)(bm0 + row) * D + kt + cc * 4);
            float4 cv = make_float4(cvt_tf32(v.x), cvt_tf32(v.y), cvt_tf32(v.z), cvt_tf32(v.w));
            *(float4*)&As[row][cc * 4] = cv;
            float4 w = *(const float4*)(Bw + (size_t)(bn0 + row) * D + kt + cc * 4);
            float4 cw = make_float4(cvt_tf32(w.x), cvt_tf32(w.y), cvt_tf32(w.z), cvt_tf32(w.w));
            *(float4*)&Bs[row][cc * 4] = cw;
        }
        __syncthreads();

#pragma unroll
        for (int ks = 0; ks < 4; ks++) {
            int k0 = ks * 8;
            uint32_t af[4][4], bf[4][2];
#pragma unroll
            for (int mt = 0; mt < 4; mt++) {
                int m = wm + mt * 16;
                af[mt][0] = __float_as_uint(As[m + g    ][k0 + tig    ]);
                af[mt][1] = __float_as_uint(As[m + g + 8][k0 + tig    ]);
                af[mt][2] = __float_as_uint(As[m + g    ][k0 + tig + 4]);
                af[mt][3] = __float_as_uint(As[m + g + 8][k0 + tig + 4]);
            }
#pragma unroll
            for (int nt = 0; nt < 4; nt++) {
                int n = wn + nt * 8;
                bf[nt][0] = __float_as_uint(Bs[n + g][k0 + tig    ]);
                bf[nt][1] = __float_as_uint(Bs[n + g][k0 + tig + 4]);
            }
#pragma unroll
            for (int mt = 0; mt < 4; mt++)
#pragma unroll
                for (int nt = 0; nt < 4; nt++)
                    mma_tf32(acc[mt][nt], af[mt], bf[nt]);
        }
        __syncthreads();
    }

#pragma unroll
    for (int mt = 0; mt < 4; mt++) {
#pragma unroll
        for (int nt = 0; nt < 4; nt++) {
            int m0 = bm0 + wm + mt * 16 + g;
            int n0 = bn0 + wn + nt * 8 + 2 * tig;
            *(float2*)&g_gx[(size_t)m0 * G4D + n0] =
                make_float2(acc[mt][nt][0], acc[mt][nt][1]);
            *(float2*)&g_gx[(size_t)(m0 + 8) * G4D + n0] =
                make_float2(acc[mt][nt][2], acc[mt][nt][3]);
        }
    }
}

// ---------------- Kreset: zero barrier state (graph-replay safe) -------------
__global__ void k_reset() {
    g_flags[threadIdx.x] = 0u;
    if (threadIdx.x == 0) g_release = 0u;
}

// ---------------- K3: persistent LSTM recurrence ------------------------------
// 128 CTAs x 512 threads. CTA owns dims [bid*4, bid*4+4) x 4 gates = 16 rows.
// Weights in registers (16 floats/thread): thread = (row = tid&15, ks = tid>>4).
// 16-way LDS broadcast on h; cp.async staging in 2 commit groups;
// flag-based grid barrier (no same-address atomic serialization).
extern __shared__ char k3_smem[];

__global__ void __launch_bounds__(512) k3_lstm(const float* __restrict__ whh,
                                               const int*   __restrict__ lengths) {
    float* s_h    = (float*)k3_smem;                       // [64][512]   131072 B
    float* s_part = (float*)(k3_smem + 131072);            // [64][16][16] 65536 B
    float* s_g    = (float*)(k3_smem + 131072 + 65536);    // [64][16]      4096 B
    uint32_t s_h_u32 = (uint32_t)__cvta_generic_to_shared(s_h);

    int tid = threadIdx.x, bid = blockIdx.x;
    int d0  = bid * 4;
    int row = tid & 15;        // row = gate*4 + dd
    int ks  = tid >> 4;        // 0..31: k-slice of 16 floats
    int w   = tid >> 5;        // warp id 0..15
    int lane = tid & 31;

    // ---- weights into registers: w[row][ks*16 .. +16] as 8 packed pairs
    unsigned long long wreg[8];
    {
        int gate = row >> 2, dd = row & 3;
        const float4* wp = (const float4*)(whh + (size_t)(gate * D + d0 + dd) * D + ks * 16);
#pragma unroll
        for (int i = 0; i < 4; i++) {
            float4 v = __ldg(wp + i);
            wreg[2*i]   = ((unsigned long long)__float_as_uint(v.y) << 32) | __float_as_uint(v.x);
            wreg[2*i+1] = ((unsigned long long)__float_as_uint(v.w) << 32) | __float_as_uint(v.z);
        }
    }
    // pointwise mapping: threads < 256 own (pb = tid>>2, pd = d0 + (tid&3))
    int pb = tid >> 2, pdd = tid & 3, pd = d0 + pdd;
    int mylen = (tid < 256) ? lengths[pb] : 0;
    float c = 0.f;

    for (int t = 0; t < S; t++) {
        // ---- stage h FIRST (2 commit groups of 32 batches each)
        if (t > 0) {
#pragma unroll
            for (int jj = 0; jj < 8; jj++) {
                int idx = tid + 512 * jj;                 // chunks 0..4095 (b 0..31)
                cpasync16(s_h_u32 + idx * 16, (const char*)g_h + (size_t)idx * 16);
            }
            cpcommit();
#pragma unroll
            for (int jj = 8; jj < 16; jj++) {
                int idx = tid + 512 * jj;                 // chunks 4096..8191 (b 32..63)
                cpasync16(s_h_u32 + idx * 16, (const char*)g_h + (size_t)idx * 16);
            }
            cpcommit();
        }

        // this step's input-projection gates (independent of h)
        float gi = 0.f, gf = 0.f, gg = 0.f, go = 0.f;
        if (tid < 256) {
            size_t gxbase = ((size_t)(t * B + pb)) * G4D + pd;
            gi = __ldg(g_gx + gxbase);
            gf = __ldg(g_gx + gxbase + D);
            gg = __ldg(g_gx + gxbase + 2 * D);
            go = __ldg(g_gx + gxbase + 3 * D);
        }

        float sg0 = 0.f, sg1 = 0.f, sg2 = 0.f, sg3 = 0.f;
        if (t > 0) {
            auto dotblock = [&](int b0) {
#pragma unroll 4
                for (int bb = 0; bb < 16; bb++) {
                    int b = b0 + bb;
                    const ulonglong2* hp = (const ulonglong2*)(s_h + b * 512 + ks * 16);
                    unsigned long long a0 = 0, a1 = 0;
#pragma unroll
                    for (int i = 0; i < 4; i++) {
                        ulonglong2 hv = hp[i];           // 16-way broadcast
                        fma2(a0, hv.x, wreg[2*i]);
                        fma2(a1, hv.y, wreg[2*i+1]);
                    }
                    float s = red2(a0) + red2(a1);
                    s += __shfl_xor_sync(0xffffffffu, s, 16);  // combine warp's 2 k-slices
                    if (lane < 16)
                        s_part[b * 256 + w * 16 + row] = s;    // conflict-free 16 floats
                }
            };
            cpwait<1>(); __syncthreads(); dotblock(0);  dotblock(16);
            cpwait<0>(); __syncthreads(); dotblock(32); dotblock(48);
            __syncthreads();

            // ---- phase 2: sum the 16 warp-partials; thread = (b2, 2 rows)
            {
                int b2 = tid >> 3, rr = (tid & 7) * 2;
                float2 a2 = make_float2(0.f, 0.f);
#pragma unroll
                for (int w2 = 0; w2 < 16; w2++) {
                    float2 v = *(const float2*)(s_part + b2 * 256 + w2 * 16 + rr);
                    a2.x += v.x; a2.y += v.y;
                }
                *(float2*)(s_g + b2 * 16 + rr) = a2;   // [b][gate*4+dd]
            }
            __syncthreads();
            if (tid < 256) {
                sg0 = s_g[pb * 16 + 0  + pdd];
                sg1 = s_g[pb * 16 + 4  + pdd];
                sg2 = s_g[pb * 16 + 8  + pdd];
                sg3 = s_g[pb * 16 + 12 + pdd];
            }
        }

        // ---- pointwise LSTM cell for (pb, pd)
        if (tid < 256) {
            float iv = fast_sigmoid(gi + sg0);
            float fv = fast_sigmoid(gf + sg1);
            float gv = fast_tanh(gg + sg2);
            float ov = fast_sigmoid(go + sg3);
            c = fv * c + iv * gv;
            float h = ov * fast_tanh(c);

            g_h[pb * D + pd] = h;
            if (t == mylen - 1) g_final[pb * D + pd] = h;
        }

        // ---- flag-based grid barrier (skip after final step)
        if (t < S - 1) {
            __syncthreads();
            unsigned v = (unsigned)(t + 1);
            if (tid == 0) {
                __threadfence();
                g_flags[bid] = v;                      // distinct addresses: parallel
            }
            if (bid == 0) {
                if (tid < 32) {
                    for (;;) {
                        bool ok = (g_flags[tid]      >= v) &&
                                  (g_flags[tid + 32] >= v) &&
                                  (g_flags[tid + 64] >= v) &&
                                  (g_flags[tid + 96] >= v);
                        if (__all_sync(0xffffffffu, ok)) break;
                    }
                    if (tid == 0) { __threadfence(); g_release = v; }
                }
            } else {
                if (tid == 0) {
                    while (g_release < v) { }
                    __threadfence();
                }
            }
            __syncthreads();
        }
    }
}

// ---------------- K4: out = final @ w_out^T + b_out --------------------------
__global__ void k4_out(const float* __restrict__ wout, const float* __restrict__ bout,
                       float* __restrict__ out) {
    int b = blockIdx.x;
    int tid = threadIdx.x;
    int o = tid >> 5, lane = tid & 31;
    float s = 0.f;
    for (int k = lane; k < D; k += 32)
        s += g_final[b * D + k] * wout[o * D + k];
#pragma unroll
    for (int off = 16; off; off >>= 1)
        s += __shfl_down_sync(0xffffffffu, s, off);
    if (lane == 0) out[b * 2 + o] = s + bout[o];
}

// ---------------- launcher ---------------------------------------------------
extern "C" void kernel_launch(void* const* d_in, const int* in_sizes, int n_in,
                              void* d_out, int out_size) {
    const int*   seqs    = (const int*)  d_in[0];
    const int*   lengths = (const int*)  d_in[1];
    const float* emb     = (const float*)d_in[2];
    const float* w_ih    = (const float*)d_in[3];
    const float* w_hh    = (const float*)d_in[4];
    const float* w_out   = (const float*)d_in[5];
    const float* b_out   = (const float*)d_in[6];
    float*       out     = (float*)d_out;

    k1_embed<<<B * S, 128>>>(seqs, emb);
    dim3 g2(G4D / 128, (B * S) / 128);   // (16, 128)
    k2_gemm<<<g2, 256>>>(w_ih);
    k_reset<<<1, 128>>>();

    const int K3_SMEM = 131072 + 65536 + 4096;   // 200704 B
    cudaFuncSetAttribute(k3_lstm, cudaFuncAttributeMaxDynamicSharedMemorySize, K3_SMEM);
    k3_lstm<<<128, 512, K3_SMEM>>>(w_hh, lengths);

    k4_out<<<B, 64>>>(w_out, b_out, out);
}

// round 11
// speedup vs baseline: 1.3199x; 1.3199x over previous
#include <cuda_runtime.h>
#include <cuda_bf16.h>
#include <cstdint>

#define VOCAB 20000
#define D     512
#define B     64
#define S     256
#define C     16
#define G4D   (4*D)      // 2048

// ---------------- scratch (device globals; no allocation allowed) ----------
__device__ float g_x[S*B*D];        // [s][b][d]
__device__ float g_gx[S*B*G4D];     // [s][b][4D]
__device__ float g_h[B*D];
__device__ float g_final[B*D];
__device__ unsigned int g_arrive;

// ---------------- helpers ---------------------------------------------------
__device__ __forceinline__ float cvt_tf32(float x) {
    uint32_t u;
    asm("cvt.rna.tf32.f32 %0, %1;" : "=r"(u) : "f"(x));
    return __uint_as_float(u);
}

__device__ __forceinline__ void mma_tf32(float* c, const uint32_t* a, const uint32_t* b) {
    asm volatile(
        "mma.sync.aligned.m16n8k8.row.col.f32.tf32.tf32.f32 "
        "{%0,%1,%2,%3}, {%4,%5,%6,%7}, {%8,%9}, {%0,%1,%2,%3};"
        : "+f"(c[0]), "+f"(c[1]), "+f"(c[2]), "+f"(c[3])
        : "r"(a[0]), "r"(a[1]), "r"(a[2]), "r"(a[3]),
          "r"(b[0]), "r"(b[1]));
}

// packed fp32x2 FMA (Blackwell): acc.lo += a.lo*b.lo ; acc.hi += a.hi*b.hi
__device__ __forceinline__ void fma2(unsigned long long& acc,
                                     unsigned long long a, unsigned long long b) {
    asm("fma.rn.f32x2 %0, %1, %2, %0;" : "+l"(acc) : "l"(a), "l"(b));
}

__device__ __forceinline__ float red2(unsigned long long a) {
    return __uint_as_float((unsigned)a) + __uint_as_float((unsigned)(a >> 32));
}

template<int N> __device__ __forceinline__ void cpwait() {
    asm volatile("cp.async.wait_group %0;" :: "n"(N) : "memory");
}
__device__ __forceinline__ void cpasync16(uint32_t dst, const void* src) {
    asm volatile("cp.async.cg.shared.global [%0], [%1], 16;" :: "r"(dst), "l"(src) : "memory");
}
__device__ __forceinline__ void cpcommit() {
    asm volatile("cp.async.commit_group;" ::: "memory");
}

// exact-ish fast activations (rel err ~2^-22; NOT the 2^-11 approx instrs)
__device__ __forceinline__ float fast_sigmoid(float x) {
    return __fdividef(1.f, 1.f + __expf(-x));
}
__device__ __forceinline__ float fast_tanh(float x) {
    float e = __expf(-2.f * fabsf(x));          // in (0,1], no overflow
    float t = __fdividef(1.f - e, 1.f + e);
    return copysignf(t, x);
}

// ---------------- K1: embedding gather + sum over codes ---------------------
__global__ void k1_embed(const int* __restrict__ seqs, const float* __restrict__ emb) {
    __shared__ int sidx[C];
    int bs  = blockIdx.x;
    int tid = threadIdx.x;
    if (tid < C) sidx[tid] = seqs[bs * C + tid];
    __syncthreads();
    int b = bs >> 8, s = bs & 255;
    float4 acc = make_float4(0.f, 0.f, 0.f, 0.f);
#pragma unroll
    for (int c = 0; c < C; c++) {
        int idx = sidx[c];
        if (idx != VOCAB) {
            float4 v = __ldg(((const float4*)(emb + (size_t)idx * D)) + tid);
            acc.x += v.x; acc.y += v.y; acc.z += v.z; acc.w += v.w;
        }
    }
    *(((float4*)(g_x + (size_t)(s * B + b) * D)) + tid) = acc;
}

// ---------------- K2: gates_x = x @ w_ih^T  (tf32 mma) -----------------------
__global__ void __launch_bounds__(256) k2_gemm(const float* __restrict__ Bw) {
    __shared__ float As[128][36];
    __shared__ float Bs[128][36];

    int tid  = threadIdx.x;
    int warp = tid >> 5, lane = tid & 31;
    int g    = lane >> 2, tig = lane & 3;
    int wm   = (warp & 1) * 64;
    int wn   = (warp >> 1) * 32;
    int bm0  = blockIdx.y * 128;
    int bn0  = blockIdx.x * 128;

    float acc[4][4][4];
#pragma unroll
    for (int mt = 0; mt < 4; mt++)
#pragma unroll
        for (int nt = 0; nt < 4; nt++)
#pragma unroll
            for (int r = 0; r < 4; r++) acc[mt][nt][r] = 0.f;

    for (int kt = 0; kt < D; kt += 32) {
#pragma unroll
        for (int i = 0; i < 4; i++) {
            int f   = tid + i * 256;
            int row = f >> 3, cc = f & 7;
            float4 v = *(const float4*)(g_x + (size_t)(bm0 + row) * D + kt + cc * 4);
            float4 cv = make_float4(cvt_tf32(v.x), cvt_tf32(v.y), cvt_tf32(v.z), cvt_tf32(v.w));
            *(float4*)&As[row][cc * 4] = cv;
            float4 w = *(const float4*)(Bw + (size_t)(bn0 + row) * D + kt + cc * 4);
            float4 cw = make_float4(cvt_tf32(w.x), cvt_tf32(w.y), cvt_tf32(w.z), cvt_tf32(w.w));
            *(float4*)&Bs[row][cc * 4] = cw;
        }
        __syncthreads();

#pragma unroll
        for (int ks = 0; ks < 4; ks++) {
            int k0 = ks * 8;
            uint32_t af[4][4], bf[4][2];
#pragma unroll
            for (int mt = 0; mt < 4; mt++) {
                int m = wm + mt * 16;
                af[mt][0] = __float_as_uint(As[m + g    ][k0 + tig    ]);
                af[mt][1] = __float_as_uint(As[m + g + 8][k0 + tig    ]);
                af[mt][2] = __float_as_uint(As[m + g    ][k0 + tig + 4]);
                af[mt][3] = __float_as_uint(As[m + g + 8][k0 + tig + 4]);
            }
#pragma unroll
            for (int nt = 0; nt < 4; nt++) {
                int n = wn + nt * 8;
                bf[nt][0] = __float_as_uint(Bs[n + g][k0 + tig    ]);
                bf[nt][1] = __float_as_uint(Bs[n + g][k0 + tig + 4]);
            }
#pragma unroll
            for (int mt = 0; mt < 4; mt++)
#pragma unroll
                for (int nt = 0; nt < 4; nt++)
                    mma_tf32(acc[mt][nt], af[mt], bf[nt]);
        }
        __syncthreads();
    }

#pragma unroll
    for (int mt = 0; mt < 4; mt++) {
#pragma unroll
        for (int nt = 0; nt < 4; nt++) {
            int m0 = bm0 + wm + mt * 16 + g;
            int n0 = bn0 + wn + nt * 8 + 2 * tig;
            *(float2*)&g_gx[(size_t)m0 * G4D + n0] =
                make_float2(acc[mt][nt][0], acc[mt][nt][1]);
            *(float2*)&g_gx[(size_t)(m0 + 8) * G4D + n0] =
                make_float2(acc[mt][nt][2], acc[mt][nt][3]);
        }
    }
}

// ---------------- Kreset ------------------------------------------------------
__global__ void k_reset() { g_arrive = 0u; }

// ---------------- K3: persistent LSTM recurrence ------------------------------
// 128 CTAs x 1024 threads (8 warps/SMSP for issue density).
// CTA owns dims [bid*4, bid*4+4) x 4 gates = 16 rows of W_hh.
// Thread = (row = tid&15, ks = (tid>>4)&31, bh = tid>>9). Weights in registers
// (16 floats/thread, duplicated across bh halves). bh=0 warps process b 0..31,
// bh=1 warps b 32..63 -> per-warp serial chain halved vs 512-thread version.
// h staged GMEM->SMEM in 4 commit groups ordered (b0-15, b32-47, b16-31, b48-63)
// so both halves start after the first wait. 16-way LDS broadcast on h.
// Reduction: shfl_xor(16) + s_part[b][16][16] + phase-2 sum. Atomic grid barrier.
extern __shared__ char k3_smem[];

__global__ void __launch_bounds__(1024) k3_lstm(const float* __restrict__ whh,
                                                const int*   __restrict__ lengths) {
    float* s_h    = (float*)k3_smem;                       // [64][512]   131072 B
    float* s_part = (float*)(k3_smem + 131072);            // [64][16][16] 65536 B
    float* s_g    = (float*)(k3_smem + 131072 + 65536);    // [64][16]      4096 B
    uint32_t s_h_u32 = (uint32_t)__cvta_generic_to_shared(s_h);

    int tid  = threadIdx.x, bid = blockIdx.x;
    int d0   = bid * 4;
    int row  = tid & 15;           // row = gate*4 + dd
    int ks   = (tid >> 4) & 31;    // k-slice of 16 floats
    int w    = tid >> 5;           // warp id 0..31
    int wprt = w & 15;             // s_part warp slot
    int bh   = tid >> 9;           // b-half: 0 -> b 0..31, 1 -> b 32..63
    int lane = tid & 31;

    // ---- weights into registers: w[row][ks*16 .. +16] as 8 packed pairs
    unsigned long long wreg[8];
    {
        int gate = row >> 2, dd = row & 3;
        const float4* wp = (const float4*)(whh + (size_t)(gate * D + d0 + dd) * D + ks * 16);
#pragma unroll
        for (int i = 0; i < 4; i++) {
            float4 v = __ldg(wp + i);
            wreg[2*i]   = ((unsigned long long)__float_as_uint(v.y) << 32) | __float_as_uint(v.x);
            wreg[2*i+1] = ((unsigned long long)__float_as_uint(v.w) << 32) | __float_as_uint(v.z);
        }
    }
    // pointwise mapping: threads < 256 own (pb = tid>>2, pd = d0 + (tid&3))
    int pb = tid >> 2, pdd = tid & 3, pd = d0 + pdd;
    int mylen = (tid < 256) ? lengths[pb] : 0;
    float c = 0.f;

    int bstart = bh ? 32 : 0;

    for (int t = 0; t < S; t++) {
        // ---- stage h FIRST: 4 commit groups of 1024 chunks (16B each)
        // group order: b0-15, b32-47, b16-31, b48-63
        if (t > 0) {
            const int goff0[2] = {0,    1024};   // b 0..15
            const int goff1[2] = {4096, 5120};   // b 32..47
            const int goff2[2] = {2048, 3072};   // b 16..31
            const int goff3[2] = {6144, 7168};   // b 48..63
#pragma unroll
            for (int j = 0; j < 2; j++) {
                int idx = tid + goff0[j];
                cpasync16(s_h_u32 + idx * 16, (const char*)g_h + (size_t)idx * 16);
            }
            cpcommit();
#pragma unroll
            for (int j = 0; j < 2; j++) {
                int idx = tid + goff1[j];
                cpasync16(s_h_u32 + idx * 16, (const char*)g_h + (size_t)idx * 16);
            }
            cpcommit();
#pragma unroll
            for (int j = 0; j < 2; j++) {
                int idx = tid + goff2[j];
                cpasync16(s_h_u32 + idx * 16, (const char*)g_h + (size_t)idx * 16);
            }
            cpcommit();
#pragma unroll
            for (int j = 0; j < 2; j++) {
                int idx = tid + goff3[j];
                cpasync16(s_h_u32 + idx * 16, (const char*)g_h + (size_t)idx * 16);
            }
            cpcommit();
        }

        // this step's input-projection gates (independent of h)
        float gi = 0.f, gf = 0.f, gg = 0.f, go = 0.f;
        if (tid < 256) {
            size_t gxbase = ((size_t)(t * B + pb)) * G4D + pd;
            gi = __ldg(g_gx + gxbase);
            gf = __ldg(g_gx + gxbase + D);
            gg = __ldg(g_gx + gxbase + 2 * D);
            go = __ldg(g_gx + gxbase + 3 * D);
        }

        float sg0 = 0.f, sg1 = 0.f, sg2 = 0.f, sg3 = 0.f;
        if (t > 0) {
            auto dotblock = [&](int b0) {
#pragma unroll 4
                for (int bb = 0; bb < 16; bb++) {
                    int b = b0 + bb;
                    const ulonglong2* hp = (const ulonglong2*)(s_h + b * 512 + ks * 16);
                    unsigned long long a0 = 0, a1 = 0;
#pragma unroll
                    for (int i = 0; i < 4; i++) {
                        ulonglong2 hv = hp[i];           // 16-way broadcast
                        fma2(a0, hv.x, wreg[2*i]);
                        fma2(a1, hv.y, wreg[2*i+1]);
                    }
                    float s = red2(a0) + red2(a1);
                    s += __shfl_xor_sync(0xffffffffu, s, 16);  // combine warp's 2 k-slices
                    if (lane < 16)
                        s_part[b * 256 + wprt * 16 + row] = s; // conflict-free 16 floats
                }
            };
            // groups 0+1 done -> both halves' first 16-b block available
            cpwait<2>(); __syncthreads();
            dotblock(bstart);
            // all groups done -> second blocks
            cpwait<0>(); __syncthreads();
            dotblock(bstart + 16);
            __syncthreads();

            // ---- phase 2: sum the 16 warp-partials; threads<512 = (b2, 2 rows)
            if (tid < 512) {
                int b2 = tid >> 3, rr = (tid & 7) * 2;
                float2 a2 = make_float2(0.f, 0.f);
#pragma unroll
                for (int w2 = 0; w2 < 16; w2++) {
                    float2 v = *(const float2*)(s_part + b2 * 256 + w2 * 16 + rr);
                    a2.x += v.x; a2.y += v.y;
                }
                *(float2*)(s_g + b2 * 16 + rr) = a2;   // [b][gate*4+dd]
            }
            __syncthreads();
            if (tid < 256) {
                sg0 = s_g[pb * 16 + 0  + pdd];
                sg1 = s_g[pb * 16 + 4  + pdd];
                sg2 = s_g[pb * 16 + 8  + pdd];
                sg3 = s_g[pb * 16 + 12 + pdd];
            }
        }

        // ---- pointwise LSTM cell for (pb, pd)
        if (tid < 256) {
            float iv = fast_sigmoid(gi + sg0);
            float fv = fast_sigmoid(gf + sg1);
            float gv = fast_tanh(gg + sg2);
            float ov = fast_sigmoid(go + sg3);
            c = fv * c + iv * gv;
            float h = ov * fast_tanh(c);

            g_h[pb * D + pd] = h;
            if (t == mylen - 1) g_final[pb * D + pd] = h;
        }

        // ---- atomic grid barrier (128 CTAs co-resident; skip after last step)
        if (t < S - 1) {
            __syncthreads();
            if (tid == 0) {
                __threadfence();
                atomicAdd(&g_arrive, 1u);
                unsigned target = (unsigned)(t + 1) * 128u;
                while (*(volatile unsigned*)&g_arrive < target) { }
                __threadfence();
            }
            __syncthreads();
        }
    }
}

// ---------------- K4: out = final @ w_out^T + b_out --------------------------
__global__ void k4_out(const float* __restrict__ wout, const float* __restrict__ bout,
                       float* __restrict__ out) {
    int b = blockIdx.x;
    int tid = threadIdx.x;
    int o = tid >> 5, lane = tid & 31;
    float s = 0.f;
    for (int k = lane; k < D; k += 32)
        s += g_final[b * D + k] * wout[o * D + k];
#pragma unroll
    for (int off = 16; off; off >>= 1)
        s += __shfl_down_sync(0xffffffffu, s, off);
    if (lane == 0) out[b * 2 + o] = s + bout[o];
}

// ---------------- launcher ---------------------------------------------------
extern "C" void kernel_launch(void* const* d_in, const int* in_sizes, int n_in,
                              void* d_out, int out_size) {
    const int*   seqs    = (const int*)  d_in[0];
    const int*   lengths = (const int*)  d_in[1];
    const float* emb     = (const float*)d_in[2];
    const float* w_ih    = (const float*)d_in[3];
    const float* w_hh    = (const float*)d_in[4];
    const float* w_out   = (const float*)d_in[5];
    const float* b_out   = (const float*)d_in[6];
    float*       out     = (float*)d_out;

    k1_embed<<<B * S, 128>>>(seqs, emb);
    dim3 g2(G4D / 128, (B * S) / 128);   // (16, 128)
    k2_gemm<<<g2, 256>>>(w_ih);
    k_reset<<<1, 1>>>();

    const int K3_SMEM = 131072 + 65536 + 4096;   // 200704 B
    cudaFuncSetAttribute(k3_lstm, cudaFuncAttributeMaxDynamicSharedMemorySize, K3_SMEM);
    k3_lstm<<<128, 1024, K3_SMEM>>>(w_hh, lengths);

    k4_out<<<B, 64>>>(w_out, b_out, out);
}

// round 16
// speedup vs baseline: 1.9947x; 1.5112x over previous
#include <cuda_runtime.h>
#include <cuda_bf16.h>
#include <cstdint>

#define VOCAB 20000
#define D     512
#define B     64
#define S     256
#define C     16
#define G4D   (4*D)      // 2048

// ---------------- scratch (device globals; no allocation allowed) ----------
__device__ float g_x[S*B*D];        // [s][b][d]
__device__ float g_gx[S*B*G4D];     // [s][b][4D]
__device__ __nv_bfloat16 g_hhi[B*D];
__device__ __nv_bfloat16 g_hlo[B*D];
__device__ float g_final[B*D];
__device__ unsigned int g_arrive;

// ---------------- helpers ---------------------------------------------------
__device__ __forceinline__ float cvt_tf32(float x) {
    uint32_t u;
    asm("cvt.rna.tf32.f32 %0, %1;" : "=r"(u) : "f"(x));
    return __uint_as_float(u);
}

__device__ __forceinline__ void mma_tf32(float* c, const uint32_t* a, const uint32_t* b) {
    asm volatile(
        "mma.sync.aligned.m16n8k8.row.col.f32.tf32.tf32.f32 "
        "{%0,%1,%2,%3}, {%4,%5,%6,%7}, {%8,%9}, {%0,%1,%2,%3};"
        : "+f"(c[0]), "+f"(c[1]), "+f"(c[2]), "+f"(c[3])
        : "r"(a[0]), "r"(a[1]), "r"(a[2]), "r"(a[3]),
          "r"(b[0]), "r"(b[1]));
}

__device__ __forceinline__ void mma_bf16(float* c, const uint32_t* a, const uint32_t* b) {
    asm volatile(
        "mma.sync.aligned.m16n8k16.row.col.f32.bf16.bf16.f32 "
        "{%0,%1,%2,%3}, {%4,%5,%6,%7}, {%8,%9}, {%0,%1,%2,%3};"
        : "+f"(c[0]), "+f"(c[1]), "+f"(c[2]), "+f"(c[3])
        : "r"(a[0]), "r"(a[1]), "r"(a[2]), "r"(a[3]),
          "r"(b[0]), "r"(b[1]));
}

__device__ __forceinline__ void ldsm_x4(uint32_t& r0, uint32_t& r1, uint32_t& r2,
                                        uint32_t& r3, uint32_t addr) {
    asm volatile("ldmatrix.sync.aligned.m8n8.x4.shared.b16 {%0,%1,%2,%3}, [%4];"
                 : "=r"(r0), "=r"(r1), "=r"(r2), "=r"(r3) : "r"(addr));
}
__device__ __forceinline__ void ldsm_x2(uint32_t& r0, uint32_t& r1, uint32_t addr) {
    asm volatile("ldmatrix.sync.aligned.m8n8.x2.shared.b16 {%0,%1}, [%2];"
                 : "=r"(r0), "=r"(r1) : "r"(addr));
}

template<int N> __device__ __forceinline__ void cpwait() {
    asm volatile("cp.async.wait_group %0;" :: "n"(N) : "memory");
}
__device__ __forceinline__ void cpasync16(uint32_t dst, const void* src) {
    asm volatile("cp.async.cg.shared.global [%0], [%1], 16;" :: "r"(dst), "l"(src) : "memory");
}
__device__ __forceinline__ void cpcommit() {
    asm volatile("cp.async.commit_group;" ::: "memory");
}

// exact-ish fast activations (rel err ~2^-22)
__device__ __forceinline__ float fast_sigmoid(float x) {
    return __fdividef(1.f, 1.f + __expf(-x));
}
__device__ __forceinline__ float fast_tanh(float x) {
    float e = __expf(-2.f * fabsf(x));
    float t = __fdividef(1.f - e, 1.f + e);
    return copysignf(t, x);
}

// ---------------- K1: embedding gather + sum over codes ---------------------
__global__ void k1_embed(const int* __restrict__ seqs, const float* __restrict__ emb) {
    __shared__ int sidx[C];
    int bs  = blockIdx.x;
    int tid = threadIdx.x;
    if (tid < C) sidx[tid] = seqs[bs * C + tid];
    __syncthreads();
    int b = bs >> 8, s = bs & 255;
    float4 acc = make_float4(0.f, 0.f, 0.f, 0.f);
#pragma unroll
    for (int c = 0; c < C; c++) {
        int idx = sidx[c];
        if (idx != VOCAB) {
            float4 v = __ldg(((const float4*)(emb + (size_t)idx * D)) + tid);
            acc.x += v.x; acc.y += v.y; acc.z += v.z; acc.w += v.w;
        }
    }
    *(((float4*)(g_x + (size_t)(s * B + b) * D)) + tid) = acc;
}

// ---------------- K2: gates_x = x @ w_ih^T  (tf32 mma) -----------------------
__global__ void __launch_bounds__(256) k2_gemm(const float* __restrict__ Bw) {
    __shared__ float As[128][36];
    __shared__ float Bs[128][36];

    int tid  = threadIdx.x;
    int warp = tid >> 5, lane = tid & 31;
    int g    = lane >> 2, tig = lane & 3;
    int wm   = (warp & 1) * 64;
    int wn   = (warp >> 1) * 32;
    int bm0  = blockIdx.y * 128;
    int bn0  = blockIdx.x * 128;

    float acc[4][4][4];
#pragma unroll
    for (int mt = 0; mt < 4; mt++)
#pragma unroll
        for (int nt = 0; nt < 4; nt++)
#pragma unroll
            for (int r = 0; r < 4; r++) acc[mt][nt][r] = 0.f;

    for (int kt = 0; kt < D; kt += 32) {
#pragma unroll
        for (int i = 0; i < 4; i++) {
            int f   = tid + i * 256;
            int row = f >> 3, cc = f & 7;
            float4 v = *(const float4*)(g_x + (size_t)(bm0 + row) * D + kt + cc * 4);
            float4 cv = make_float4(cvt_tf32(v.x), cvt_tf32(v.y), cvt_tf32(v.z), cvt_tf32(v.w));
            *(float4*)&As[row][cc * 4] = cv;
            float4 w = *(const float4*)(Bw + (size_t)(bn0 + row) * D + kt + cc * 4);
            float4 cw = make_float4(cvt_tf32(w.x), cvt_tf32(w.y), cvt_tf32(w.z), cvt_tf32(w.w));
            *(float4*)&Bs[row][cc * 4] = cw;
        }
        __syncthreads();

#pragma unroll
        for (int ks = 0; ks < 4; ks++) {
            int k0 = ks * 8;
            uint32_t af[4][4], bf[4][2];
#pragma unroll
            for (int mt = 0; mt < 4; mt++) {
                int m = wm + mt * 16;
                af[mt][0] = __float_as_uint(As[m + g    ][k0 + tig    ]);
                af[mt][1] = __float_as_uint(As[m + g + 8][k0 + tig    ]);
                af[mt][2] = __float_as_uint(As[m + g    ][k0 + tig + 4]);
                af[mt][3] = __float_as_uint(As[m + g + 8][k0 + tig + 4]);
            }
#pragma unroll
            for (int nt = 0; nt < 4; nt++) {
                int n = wn + nt * 8;
                bf[nt][0] = __float_as_uint(Bs[n + g][k0 + tig    ]);
                bf[nt][1] = __float_as_uint(Bs[n + g][k0 + tig + 4]);
            }
#pragma unroll
            for (int mt = 0; mt < 4; mt++)
#pragma unroll
                for (int nt = 0; nt < 4; nt++)
                    mma_tf32(acc[mt][nt], af[mt], bf[nt]);
        }
        __syncthreads();
    }

#pragma unroll
    for (int mt = 0; mt < 4; mt++) {
#pragma unroll
        for (int nt = 0; nt < 4; nt++) {
            int m0 = bm0 + wm + mt * 16 + g;
            int n0 = bn0 + wn + nt * 8 + 2 * tig;
            *(float2*)&g_gx[(size_t)m0 * G4D + n0] =
                make_float2(acc[mt][nt][0], acc[mt][nt][1]);
            *(float2*)&g_gx[(size_t)(m0 + 8) * G4D + n0] =
                make_float2(acc[mt][nt][2], acc[mt][nt][3]);
        }
    }
}

// ---------------- Kreset ------------------------------------------------------
__global__ void k_reset() { g_arrive = 0u; }

// ---------------- K3: persistent LSTM recurrence (bf16-split tensor cores) ----
// 128 CTAs x 512 threads = 16 warps. Warp = (mt = w&3 : 16-b tile, kq = w>>2 :
// 128-k quarter). Each step: warp stages ITS OWN (mt,kq) block of h_hi/h_lo via
// cp.async (self-contained -> cpwait + __syncwarp only), then 8 k-steps of
// m16n8k16 bf16 mma: C += Ahi*Bhi + Ahi*Blo + Alo*Bhi (fp32 accum, ~fp32 acc).
// Weights pre-split to SMEM bf16 hi/lo once. Partials s_g[4][64][20] summed by
// the 256 pointwise threads, which also write h back as split bf16 pair.
#define HSTR   1040                     // smem row stride bytes (4-bank shift/row -> ldsm conflict-free)
#define SH_HI  0
#define SH_LO  66560                    // 64*1040
#define SW_OFF 133120                   // weights: [2][16][HSTR]
#define SG_OFF 166400                   // partials: [4][64][20] f32
#define K3_SMEM_TOTAL (166400 + 4*64*20*4)   // 186880

extern __shared__ char k3_smem[];

__global__ void __launch_bounds__(512) k3_lstm(const float* __restrict__ whh,
                                               const int*   __restrict__ lengths) {
    char* smc = k3_smem;
    uint32_t sbase = (uint32_t)__cvta_generic_to_shared(smc);

    int tid  = threadIdx.x, bid = blockIdx.x;
    int d0   = bid * 4;
    int w    = tid >> 5, lane = tid & 31;
    int mt   = w & 3;              // b-tile: rows mt*16 .. +16
    int kq   = w >> 2;             // k-quarter: k in [kq*128, kq*128+128)
    int g    = lane >> 2, tg = lane & 3;

    // ---- split weights into SMEM bf16 hi/lo: s_w[sel][r][k], r = gate*4+dd
    for (int j = tid; j < 16 * D; j += 512) {
        int r = j >> 9, k = j & 511;
        int R = (r >> 2) * D + d0 + (r & 3);
        float x = __ldg(whh + (size_t)R * D + k);
        __nv_bfloat16 hi = __float2bfloat16(x);
        __nv_bfloat16 lo = __float2bfloat16(x - __bfloat162float(hi));
        *(__nv_bfloat16*)(smc + SW_OFF +         r * HSTR + k * 2) = hi;
        *(__nv_bfloat16*)(smc + SW_OFF + 16640 + r * HSTR + k * 2) = lo;
    }

    // pointwise mapping: threads < 256 own (pb = tid>>2, pd = d0 + (tid&3))
    int pb = tid >> 2, pdd = tid & 3, pd = d0 + pdd;
    int mylen = (tid < 256) ? lengths[pb] : 0;
    float c = 0.f;
    __syncthreads();

    // ---- per-lane ldmatrix addresses (advance by 32B per k-step)
    uint32_t a_hi = sbase + SH_HI + (mt * 16 + (lane & 15)) * HSTR
                  + ((lane >> 4) & 1) * 16 + kq * 256;
    uint32_t a_lo = a_hi + (SH_LO - SH_HI);
    uint32_t bro  = (lane & 7) * HSTR + ((lane >> 3) & 1) * 16 + kq * 256;
    uint32_t b_hi0 = sbase + SW_OFF + bro;                 // n rows 0..7, hi
    uint32_t b_hi1 = b_hi0 + 8 * HSTR;                     // n rows 8..15, hi
    uint32_t b_lo0 = b_hi0 + 16640;
    uint32_t b_lo1 = b_hi1 + 16640;

    for (int t = 0; t < S; t++) {
        // this step's input-projection gates (independent of h)
        float gi = 0.f, gf = 0.f, gg = 0.f, go = 0.f;
        if (tid < 256) {
            size_t gxbase = ((size_t)(t * B + pb)) * G4D + pd;
            gi = __ldg(g_gx + gxbase);
            gf = __ldg(g_gx + gxbase + D);
            gg = __ldg(g_gx + gxbase + 2 * D);
            go = __ldg(g_gx + gxbase + 3 * D);
        }

        if (t > 0) {
            // ---- stage this warp's (mt,kq) h-block: 512 chunks x 16B (hi+lo)
#pragma unroll
            for (int j = 0; j < 16; j++) {
                int id  = j * 32 + lane;           // 0..511
                int sel = id >> 8;                 // 0 = hi, 1 = lo
                int cid = id & 255;
                int row = cid >> 4, cc = cid & 15;
                const char* src = (sel ? (const char*)g_hlo : (const char*)g_hhi)
                                + (size_t)(mt * 16 + row) * (D * 2) + kq * 256 + cc * 16;
                uint32_t dst = sbase + (sel ? SH_LO : SH_HI)
                             + (mt * 16 + row) * HSTR + kq * 256 + cc * 16;
                cpasync16(dst, src);
            }
            cpcommit();
            cpwait<0>();
            __syncwarp();

            // ---- mma: C[m16][n16] over k128, 3-term bf16 split
            float Ca[4] = {0.f, 0.f, 0.f, 0.f};   // n cols 0..7
            float Cb[4] = {0.f, 0.f, 0.f, 0.f};   // n cols 8..15
#pragma unroll
            for (int kk = 0; kk < 8; kk++) {
                uint32_t kb = kk * 32;
                uint32_t ah[4], al[4], bh0[2], bh1[2], bl0[2], bl1[2];
                ldsm_x4(ah[0], ah[1], ah[2], ah[3], a_hi + kb);
                ldsm_x4(al[0], al[1], al[2], al[3], a_lo + kb);
                ldsm_x2(bh0[0], bh0[1], b_hi0 + kb);
                ldsm_x2(bh1[0], bh1[1], b_hi1 + kb);
                ldsm_x2(bl0[0], bl0[1], b_lo0 + kb);
                ldsm_x2(bl1[0], bl1[1], b_lo1 + kb);
                mma_bf16(Ca, ah, bh0);
                mma_bf16(Ca, ah, bl0);
                mma_bf16(Ca, al, bh0);
                mma_bf16(Cb, ah, bh1);
                mma_bf16(Cb, ah, bl1);
                mma_bf16(Cb, al, bh1);
            }
            // ---- epilogue: stash partials s_g[kq][b][20]
            {
                char* sg = smc + SG_OFF + kq * 5120 + (mt * 16 + g) * 80;
                *(float2*)(sg + (2 * tg) * 4)           = make_float2(Ca[0], Ca[1]);
                *(float2*)(sg + (8 + 2 * tg) * 4)       = make_float2(Cb[0], Cb[1]);
                *(float2*)(sg + 640 + (2 * tg) * 4)     = make_float2(Ca[2], Ca[3]);
                *(float2*)(sg + 640 + (8 + 2 * tg) * 4) = make_float2(Cb[2], Cb[3]);
            }
        }
        __syncthreads();

        // ---- pointwise LSTM cell for (pb, pd)
        if (tid < 256) {
            float sg0 = 0.f, sg1 = 0.f, sg2 = 0.f, sg3 = 0.f;
            if (t > 0) {
#pragma unroll
                for (int q = 0; q < 4; q++) {
                    const float* p = (const float*)(smc + SG_OFF + q * 5120 + pb * 80);
                    sg0 += p[0  + pdd];
                    sg1 += p[4  + pdd];
                    sg2 += p[8  + pdd];
                    sg3 += p[12 + pdd];
                }
            }
            float iv = fast_sigmoid(gi + sg0);
            float fv = fast_sigmoid(gf + sg1);
            float gv = fast_tanh(gg + sg2);
            float ov = fast_sigmoid(go + sg3);
            c = fv * c + iv * gv;
            float h = ov * fast_tanh(c);

            __nv_bfloat16 hi = __float2bfloat16(h);
            __nv_bfloat16 lo = __float2bfloat16(h - __bfloat162float(hi));
            g_hhi[pb * D + pd] = hi;
            g_hlo[pb * D + pd] = lo;
            if (t == mylen - 1) g_final[pb * D + pd] = h;
        }

        // ---- atomic grid barrier (128 CTAs co-resident; skip after last step)
        if (t < S - 1) {
            __syncthreads();
            if (tid == 0) {
                __threadfence();
                atomicAdd(&g_arrive, 1u);
                unsigned target = (unsigned)(t + 1) * 128u;
                while (*(volatile unsigned*)&g_arrive < target) { }
                __threadfence();
            }
            __syncthreads();
        }
    }
}

// ---------------- K4: out = final @ w_out^T + b_out --------------------------
__global__ void k4_out(const float* __restrict__ wout, const float* __restrict__ bout,
                       float* __restrict__ out) {
    int b = blockIdx.x;
    int tid = threadIdx.x;
    int o = tid >> 5, lane = tid & 31;
    float s = 0.f;
    for (int k = lane; k < D; k += 32)
        s += g_final[b * D + k] * wout[o * D + k];
#pragma unroll
    for (int off = 16; off; off >>= 1)
        s += __shfl_down_sync(0xffffffffu, s, off);
    if (lane == 0) out[b * 2 + o] = s + bout[o];
}

// ---------------- launcher ---------------------------------------------------
extern "C" void kernel_launch(void* const* d_in, const int* in_sizes, int n_in,
                              void* d_out, int out_size) {
    const int*   seqs    = (const int*)  d_in[0];
    const int*   lengths = (const int*)  d_in[1];
    const float* emb     = (const float*)d_in[2];
    const float* w_ih    = (const float*)d_in[3];
    const float* w_hh    = (const float*)d_in[4];
    const float* w_out   = (const float*)d_in[5];
    const float* b_out   = (const float*)d_in[6];
    float*       out     = (float*)d_out;

    k1_embed<<<B * S, 128>>>(seqs, emb);
    dim3 g2(G4D / 128, (B * S) / 128);   // (16, 128)
    k2_gemm<<<g2, 256>>>(w_ih);
    k_reset<<<1, 1>>>();

    cudaFuncSetAttribute(k3_lstm, cudaFuncAttributeMaxDynamicSharedMemorySize,
                         K3_SMEM_TOTAL);
    k3_lstm<<<128, 512, K3_SMEM_TOTAL>>>(w_hh, lengths);

    k4_out<<<B, 64>>>(w_out, b_out, out);
}

// round 17
// speedup vs baseline: 2.1061x; 1.0559x over previous
#include <cuda_runtime.h>
#include <cuda_bf16.h>
#include <cstdint>

#define VOCAB 20000
#define D     512
#define B     64
#define S     256
#define C     16
#define G4D   (4*D)      // 2048

// ---------------- scratch (device globals; no allocation allowed) ----------
__device__ float g_x[S*B*D];        // [s][b][d]
__device__ float g_gx[S*B*G4D];     // [s][b][4D]
__device__ __nv_bfloat16 g_hhi[B*D];
__device__ __nv_bfloat16 g_hlo[B*D];
__device__ float g_final[B*D];
__device__ unsigned int g_arrive;

// ---------------- helpers ---------------------------------------------------
__device__ __forceinline__ float cvt_tf32(float x) {
    uint32_t u;
    asm("cvt.rna.tf32.f32 %0, %1;" : "=r"(u) : "f"(x));
    return __uint_as_float(u);
}

__device__ __forceinline__ void mma_tf32(float* c, const uint32_t* a, const uint32_t* b) {
    asm volatile(
        "mma.sync.aligned.m16n8k8.row.col.f32.tf32.tf32.f32 "
        "{%0,%1,%2,%3}, {%4,%5,%6,%7}, {%8,%9}, {%0,%1,%2,%3};"
        : "+f"(c[0]), "+f"(c[1]), "+f"(c[2]), "+f"(c[3])
        : "r"(a[0]), "r"(a[1]), "r"(a[2]), "r"(a[3]),
          "r"(b[0]), "r"(b[1]));
}

__device__ __forceinline__ void mma_bf16(float* c, const uint32_t* a, const uint32_t* b) {
    asm volatile(
        "mma.sync.aligned.m16n8k16.row.col.f32.bf16.bf16.f32 "
        "{%0,%1,%2,%3}, {%4,%5,%6,%7}, {%8,%9}, {%0,%1,%2,%3};"
        : "+f"(c[0]), "+f"(c[1]), "+f"(c[2]), "+f"(c[3])
        : "r"(a[0]), "r"(a[1]), "r"(a[2]), "r"(a[3]),
          "r"(b[0]), "r"(b[1]));
}

__device__ __forceinline__ void ldsm_x4(uint32_t& r0, uint32_t& r1, uint32_t& r2,
                                        uint32_t& r3, uint32_t addr) {
    asm volatile("ldmatrix.sync.aligned.m8n8.x4.shared.b16 {%0,%1,%2,%3}, [%4];"
                 : "=r"(r0), "=r"(r1), "=r"(r2), "=r"(r3) : "r"(addr));
}
__device__ __forceinline__ void ldsm_x2(uint32_t& r0, uint32_t& r1, uint32_t addr) {
    asm volatile("ldmatrix.sync.aligned.m8n8.x2.shared.b16 {%0,%1}, [%2];"
                 : "=r"(r0), "=r"(r1) : "r"(addr));
}

template<int N> __device__ __forceinline__ void cpwait() {
    asm volatile("cp.async.wait_group %0;" :: "n"(N) : "memory");
}
__device__ __forceinline__ void cpasync16(uint32_t dst, const void* src) {
    asm volatile("cp.async.cg.shared.global [%0], [%1], 16;" :: "r"(dst), "l"(src) : "memory");
}
__device__ __forceinline__ void cpcommit() {
    asm volatile("cp.async.commit_group;" ::: "memory");
}

// exact-ish fast activations (rel err ~2^-22)
__device__ __forceinline__ float fast_sigmoid(float x) {
    return __fdividef(1.f, 1.f + __expf(-x));
}
__device__ __forceinline__ float fast_tanh(float x) {
    float e = __expf(-2.f * fabsf(x));
    float t = __fdividef(1.f - e, 1.f + e);
    return copysignf(t, x);
}

// ---------------- K1: embedding gather + sum over codes ---------------------
__global__ void k1_embed(const int* __restrict__ seqs, const float* __restrict__ emb) {
    __shared__ int sidx[C];
    int bs  = blockIdx.x;
    int tid = threadIdx.x;
    if (tid < C) sidx[tid] = seqs[bs * C + tid];
    __syncthreads();
    int b = bs >> 8, s = bs & 255;
    float4 acc = make_float4(0.f, 0.f, 0.f, 0.f);
#pragma unroll
    for (int c = 0; c < C; c++) {
        int idx = sidx[c];
        if (idx != VOCAB) {
            float4 v = __ldg(((const float4*)(emb + (size_t)idx * D)) + tid);
            acc.x += v.x; acc.y += v.y; acc.z += v.z; acc.w += v.w;
        }
    }
    *(((float4*)(g_x + (size_t)(s * B + b) * D)) + tid) = acc;
}

// ---------------- K2: gates_x = x @ w_ih^T  (tf32 mma) -----------------------
__global__ void __launch_bounds__(256) k2_gemm(const float* __restrict__ Bw) {
    __shared__ float As[128][36];
    __shared__ float Bs[128][36];

    int tid  = threadIdx.x;
    int warp = tid >> 5, lane = tid & 31;
    int g    = lane >> 2, tig = lane & 3;
    int wm   = (warp & 1) * 64;
    int wn   = (warp >> 1) * 32;
    int bm0  = blockIdx.y * 128;
    int bn0  = blockIdx.x * 128;

    float acc[4][4][4];
#pragma unroll
    for (int mt = 0; mt < 4; mt++)
#pragma unroll
        for (int nt = 0; nt < 4; nt++)
#pragma unroll
            for (int r = 0; r < 4; r++) acc[mt][nt][r] = 0.f;

    for (int kt = 0; kt < D; kt += 32) {
#pragma unroll
        for (int i = 0; i < 4; i++) {
            int f   = tid + i * 256;
            int row = f >> 3, cc = f & 7;
            float4 v = *(const float4*)(g_x + (size_t)(bm0 + row) * D + kt + cc * 4);
            float4 cv = make_float4(cvt_tf32(v.x), cvt_tf32(v.y), cvt_tf32(v.z), cvt_tf32(v.w));
            *(float4*)&As[row][cc * 4] = cv;
            float4 w = *(const float4*)(Bw + (size_t)(bn0 + row) * D + kt + cc * 4);
            float4 cw = make_float4(cvt_tf32(w.x), cvt_tf32(w.y), cvt_tf32(w.z), cvt_tf32(w.w));
            *(float4*)&Bs[row][cc * 4] = cw;
        }
        __syncthreads();

#pragma unroll
        for (int ks = 0; ks < 4; ks++) {
            int k0 = ks * 8;
            uint32_t af[4][4], bf[4][2];
#pragma unroll
            for (int mt = 0; mt < 4; mt++) {
                int m = wm + mt * 16;
                af[mt][0] = __float_as_uint(As[m + g    ][k0 + tig    ]);
                af[mt][1] = __float_as_uint(As[m + g + 8][k0 + tig    ]);
                af[mt][2] = __float_as_uint(As[m + g    ][k0 + tig + 4]);
                af[mt][3] = __float_as_uint(As[m + g + 8][k0 + tig + 4]);
            }
#pragma unroll
            for (int nt = 0; nt < 4; nt++) {
                int n = wn + nt * 8;
                bf[nt][0] = __float_as_uint(Bs[n + g][k0 + tig    ]);
                bf[nt][1] = __float_as_uint(Bs[n + g][k0 + tig + 4]);
            }
#pragma unroll
            for (int mt = 0; mt < 4; mt++)
#pragma unroll
                for (int nt = 0; nt < 4; nt++)
                    mma_tf32(acc[mt][nt], af[mt], bf[nt]);
        }
        __syncthreads();
    }

#pragma unroll
    for (int mt = 0; mt < 4; mt++) {
#pragma unroll
        for (int nt = 0; nt < 4; nt++) {
            int m0 = bm0 + wm + mt * 16 + g;
            int n0 = bn0 + wn + nt * 8 + 2 * tig;
            *(float2*)&g_gx[(size_t)m0 * G4D + n0] =
                make_float2(acc[mt][nt][0], acc[mt][nt][1]);
            *(float2*)&g_gx[(size_t)(m0 + 8) * G4D + n0] =
                make_float2(acc[mt][nt][2], acc[mt][nt][3]);
        }
    }
}

// ---------------- Kreset ------------------------------------------------------
__global__ void k_reset() { g_arrive = 0u; }

// ---------------- K3: persistent LSTM recurrence (bf16-split tensor cores) ----
// 128 CTAs x 512 threads = 16 warps. Warp = (mt = w&3 : 16-b tile, kq = w>>2 :
// 128-k quarter). Per step: warp stages ITS OWN (mt,kq) h-block in TWO commit
// groups (k-halves) and pipelines mma kk 0..3 under the second half's landing.
// 3-term bf16-split mma (Ahi*Bhi + Ahi*Blo + Alo*Bhi, fp32 accum) on FOUR
// independent accumulator chains. Weights pre-split to SMEM bf16 hi/lo once.
// Partials s_g[4][64][20] summed by the 256 pointwise threads.
#define HSTR   1040                     // smem row stride bytes (4-bank shift/row -> ldsm conflict-free)
#define SH_HI  0
#define SH_LO  66560                    // 64*1040
#define SW_OFF 133120                   // weights: [2][16][HSTR]
#define SG_OFF 166400                   // partials: [4][64][20] f32
#define K3_SMEM_TOTAL (166400 + 4*64*20*4)   // 186880

extern __shared__ char k3_smem[];

__global__ void __launch_bounds__(512) k3_lstm(const float* __restrict__ whh,
                                               const int*   __restrict__ lengths) {
    char* smc = k3_smem;
    uint32_t sbase = (uint32_t)__cvta_generic_to_shared(smc);

    int tid  = threadIdx.x, bid = blockIdx.x;
    int d0   = bid * 4;
    int w    = tid >> 5, lane = tid & 31;
    int mt   = w & 3;              // b-tile: rows mt*16 .. +16
    int kq   = w >> 2;             // k-quarter: k in [kq*128, kq*128+128)
    int g    = lane >> 2, tg = lane & 3;

    // ---- split weights into SMEM bf16 hi/lo: s_w[sel][r][k], r = gate*4+dd
    for (int j = tid; j < 16 * D; j += 512) {
        int r = j >> 9, k = j & 511;
        int R = (r >> 2) * D + d0 + (r & 3);
        float x = __ldg(whh + (size_t)R * D + k);
        __nv_bfloat16 hi = __float2bfloat16(x);
        __nv_bfloat16 lo = __float2bfloat16(x - __bfloat162float(hi));
        *(__nv_bfloat16*)(smc + SW_OFF +         r * HSTR + k * 2) = hi;
        *(__nv_bfloat16*)(smc + SW_OFF + 16640 + r * HSTR + k * 2) = lo;
    }

    // pointwise mapping: threads < 256 own (pb = tid>>2, pd = d0 + (tid&3))
    int pb = tid >> 2, pdd = tid & 3, pd = d0 + pdd;
    int mylen = (tid < 256) ? lengths[pb] : 0;
    float c = 0.f;
    __syncthreads();

    // ---- per-lane ldmatrix addresses (advance by 32B per k-step)
    uint32_t a_hi = sbase + SH_HI + (mt * 16 + (lane & 15)) * HSTR
                  + ((lane >> 4) & 1) * 16 + kq * 256;
    uint32_t a_lo = a_hi + (SH_LO - SH_HI);
    uint32_t bro  = (lane & 7) * HSTR + ((lane >> 3) & 1) * 16 + kq * 256;
    uint32_t b_hi0 = sbase + SW_OFF + bro;                 // n rows 0..7, hi
    uint32_t b_hi1 = b_hi0 + 8 * HSTR;                     // n rows 8..15, hi
    uint32_t b_lo0 = b_hi0 + 16640;
    uint32_t b_lo1 = b_hi1 + 16640;

    for (int t = 0; t < S; t++) {
        float Ca0[4] = {0.f,0.f,0.f,0.f}, Ca1[4] = {0.f,0.f,0.f,0.f};
        float Cb0[4] = {0.f,0.f,0.f,0.f}, Cb1[4] = {0.f,0.f,0.f,0.f};

        if (t > 0) {
            // ---- stage this warp's (mt,kq) h-block in TWO k-half groups
            // group A: cc 0..7 (k bytes [0,128)), hi+lo = 256 chunks
#pragma unroll
            for (int j = 0; j < 8; j++) {
                int idx = j * 32 + lane;          // 0..255
                int sel = idx >> 7;               // 0 = hi, 1 = lo
                int rem = idx & 127;
                int row = rem >> 3, cc = rem & 7;
                const char* src = (sel ? (const char*)g_hlo : (const char*)g_hhi)
                                + (size_t)(mt * 16 + row) * (D * 2) + kq * 256 + cc * 16;
                uint32_t dst = sbase + (sel ? SH_LO : SH_HI)
                             + (mt * 16 + row) * HSTR + kq * 256 + cc * 16;
                cpasync16(dst, src);
            }
            cpcommit();
            // group B: cc 8..15 (k bytes [128,256))
#pragma unroll
            for (int j = 0; j < 8; j++) {
                int idx = j * 32 + lane;
                int sel = idx >> 7;
                int rem = idx & 127;
                int row = rem >> 3, cc = (rem & 7) + 8;
                const char* src = (sel ? (const char*)g_hlo : (const char*)g_hhi)
                                + (size_t)(mt * 16 + row) * (D * 2) + kq * 256 + cc * 16;
                uint32_t dst = sbase + (sel ? SH_LO : SH_HI)
                             + (mt * 16 + row) * HSTR + kq * 256 + cc * 16;
                cpasync16(dst, src);
            }
            cpcommit();
        }

        // this step's input-projection gates (independent of h; overlaps staging)
        float gi = 0.f, gf = 0.f, gg = 0.f, go = 0.f;
        if (tid < 256) {
            size_t gxbase = ((size_t)(t * B + pb)) * G4D + pd;
            gi = __ldg(g_gx + gxbase);
            gf = __ldg(g_gx + gxbase + D);
            gg = __ldg(g_gx + gxbase + 2 * D);
            go = __ldg(g_gx + gxbase + 3 * D);
        }

        if (t > 0) {
            auto mma_half = [&](int kk0) {
#pragma unroll
                for (int kk = kk0; kk < kk0 + 4; kk++) {
                    uint32_t kb = kk * 32;
                    uint32_t ah[4], al[4], bh0[2], bh1[2], bl0[2], bl1[2];
                    ldsm_x4(ah[0], ah[1], ah[2], ah[3], a_hi + kb);
                    ldsm_x4(al[0], al[1], al[2], al[3], a_lo + kb);
                    ldsm_x2(bh0[0], bh0[1], b_hi0 + kb);
                    ldsm_x2(bh1[0], bh1[1], b_hi1 + kb);
                    ldsm_x2(bl0[0], bl0[1], b_lo0 + kb);
                    ldsm_x2(bl1[0], bl1[1], b_lo1 + kb);
                    mma_bf16(Ca0, ah, bh0);
                    mma_bf16(Ca1, ah, bl0);
                    mma_bf16(Ca1, al, bh0);
                    mma_bf16(Cb0, ah, bh1);
                    mma_bf16(Cb1, ah, bl1);
                    mma_bf16(Cb1, al, bh1);
                }
            };
            cpwait<1>(); __syncwarp();
            mma_half(0);                 // overlaps group B's landing
            cpwait<0>(); __syncwarp();
            mma_half(4);

            // ---- epilogue: merge chains, stash partials s_g[kq][b][20]
            {
                char* sg = smc + SG_OFF + kq * 5120 + (mt * 16 + g) * 80;
                *(float2*)(sg + (2 * tg) * 4) =
                    make_float2(Ca0[0] + Ca1[0], Ca0[1] + Ca1[1]);
                *(float2*)(sg + (8 + 2 * tg) * 4) =
                    make_float2(Cb0[0] + Cb1[0], Cb0[1] + Cb1[1]);
                *(float2*)(sg + 640 + (2 * tg) * 4) =
                    make_float2(Ca0[2] + Ca1[2], Ca0[3] + Ca1[3]);
                *(float2*)(sg + 640 + (8 + 2 * tg) * 4) =
                    make_float2(Cb0[2] + Cb1[2], Cb0[3] + Cb1[3]);
            }
        }
        __syncthreads();

        // ---- pointwise LSTM cell for (pb, pd)
        if (tid < 256) {
            float sg0 = 0.f, sg1 = 0.f, sg2 = 0.f, sg3 = 0.f;
            if (t > 0) {
#pragma unroll
                for (int q = 0; q < 4; q++) {
                    const float* p = (const float*)(smc + SG_OFF + q * 5120 + pb * 80);
                    sg0 += p[0  + pdd];
                    sg1 += p[4  + pdd];
                    sg2 += p[8  + pdd];
                    sg3 += p[12 + pdd];
                }
            }
            float iv = fast_sigmoid(gi + sg0);
            float fv = fast_sigmoid(gf + sg1);
            float gv = fast_tanh(gg + sg2);
            float ov = fast_sigmoid(go + sg3);
            c = fv * c + iv * gv;
            float h = ov * fast_tanh(c);

            __nv_bfloat16 hi = __float2bfloat16(h);
            __nv_bfloat16 lo = __float2bfloat16(h - __bfloat162float(hi));
            g_hhi[pb * D + pd] = hi;
            g_hlo[pb * D + pd] = lo;
            if (t == mylen - 1) g_final[pb * D + pd] = h;
        }

        // ---- atomic grid barrier (128 CTAs co-resident; skip after last step)
        if (t < S - 1) {
            __syncthreads();
            if (tid == 0) {
                __threadfence();
                atomicAdd(&g_arrive, 1u);
                unsigned target = (unsigned)(t + 1) * 128u;
                while (*(volatile unsigned*)&g_arrive < target) { }
                __threadfence();
            }
            __syncthreads();
        }
    }
}

// ---------------- K4: out = final @ w_out^T + b_out --------------------------
__global__ void k4_out(const float* __restrict__ wout, const float* __restrict__ bout,
                       float* __restrict__ out) {
    int b = blockIdx.x;
    int tid = threadIdx.x;
    int o = tid >> 5, lane = tid & 31;
    float s = 0.f;
    for (int k = lane; k < D; k += 32)
        s += g_final[b * D + k] * wout[o * D + k];
#pragma unroll
    for (int off = 16; off; off >>= 1)
        s += __shfl_down_sync(0xffffffffu, s, off);
    if (lane == 0) out[b * 2 + o] = s + bout[o];
}

// ---------------- launcher ---------------------------------------------------
extern "C" void kernel_launch(void* const* d_in, const int* in_sizes, int n_in,
                              void* d_out, int out_size) {
    const int*   seqs    = (const int*)  d_in[0];
    const int*   lengths = (const int*)  d_in[1];
    const float* emb     = (const float*)d_in[2];
    const float* w_ih    = (const float*)d_in[3];
    const float* w_hh    = (const float*)d_in[4];
    const float* w_out   = (const float*)d_in[5];
    const float* b_out   = (const float*)d_in[6];
    float*       out     = (float*)d_out;

    k1_embed<<<B * S, 128>>>(seqs, emb);
    dim3 g2(G4D / 128, (B * S) / 128);   // (16, 128)
    k2_gemm<<<g2, 256>>>(w_ih);
    k_reset<<<1, 1>>>();

    cudaFuncSetAttribute(k3_lstm, cudaFuncAttributeMaxDynamicSharedMemorySize,
                         K3_SMEM_TOTAL);
    k3_lstm<<<128, 512, K3_SMEM_TOTAL>>>(w_hh, lengths);

    k4_out<<<B, 64>>>(w_out, b_out, out);
}